// round 2
// baseline (speedup 1.0000x reference)
#include <cuda_runtime.h>

// Problem constants (fixed shapes from reference_code)
constexpr int N_ = 50000;     // nodes
constexpr int E_ = 800000;    // edges
// LAGS=16, FILT=64, K=2, CIN=80 — but H0==0 kills hidden channels entirely.

// Scratch (no device allocation allowed -> __device__ globals)
__device__ float g_deg_out[N_];
__device__ float g_deg_in[N_];
__device__ float g_txo[N_ * 16];
__device__ float g_txi[N_ * 16];

__global__ void zero_kernel() {
    int i = blockIdx.x * blockDim.x + threadIdx.x;
    if (i < N_ * 16) { g_txo[i] = 0.f; g_txi[i] = 0.f; }
    if (i < N_)      { g_deg_out[i] = 0.f; g_deg_in[i] = 0.f; }
}

__global__ void degree_kernel(const int* __restrict__ ei,
                              const float* __restrict__ ew) {
    int e = blockIdx.x * blockDim.x + threadIdx.x;
    if (e >= E_) return;
    int r = ei[e];
    int c = ei[E_ + e];
    float w = ew[e];
    atomicAdd(&g_deg_out[r], w);
    atomicAdd(&g_deg_in[c], w);
}

// One thread per (edge, quarter-row). Gathers x[row]/x[col] (L2-resident),
// scales by 1/deg, scatters 4 floats into each of txo/txi via atomics.
__global__ void scatter_kernel(const int* __restrict__ ei,
                               const float* __restrict__ x) {
    int t = blockIdx.x * blockDim.x + threadIdx.x;
    if (t >= E_ * 4) return;
    int e = t >> 2;
    int q = t & 3;
    int r = ei[e];
    int c = ei[E_ + e];

    float d_o = g_deg_out[r]; d_o = (d_o > 0.f) ? d_o : 1.f;
    float d_i = g_deg_in[c];  d_i = (d_i > 0.f) ? d_i : 1.f;
    float no = 1.f / d_o;
    float ni = 1.f / d_i;

    const float4* x4 = reinterpret_cast<const float4*>(x);
    float4 xr = x4[r * 4 + q];   // x[row], 16B chunk q
    float4 xc = x4[c * 4 + q];   // x[col], 16B chunk q

    float* po = &g_txo[c * 16 + q * 4];
    atomicAdd(po + 0, no * xr.x);
    atomicAdd(po + 1, no * xr.y);
    atomicAdd(po + 2, no * xr.z);
    atomicAdd(po + 3, no * xr.w);

    float* pi = &g_txi[r * 16 + q * 4];
    atomicAdd(pi + 0, ni * xc.x);
    atomicAdd(pi + 1, ni * xc.y);
    atomicAdd(pi + 2, ni * xc.z);
    atomicAdd(pi + 3, ni * xc.w);
}

// Per-node fused epilogue:
//   F = [x, Tx_o, Tx_i] (48)
//   pre_z = F @ Wz_eff + b_z ; pre_h = F @ Wh_eff + b_h   (48x64 each)
//   out = sum_j relu( (1 - sigmoid(pre_z_j)) * tanh(pre_h_j) ) * lin_w_j + lin_b
// Wz_eff rows: [0:16) = Wz[0,0,:16]+Wz[1,0,:16]; [16:32) = Wz[0,1,:16]; [32:48) = Wz[1,1,:16]
__global__ void node_kernel(const float* __restrict__ x,
                            const float* __restrict__ w_z, const float* __restrict__ b_z,
                            const float* __restrict__ w_h, const float* __restrict__ b_h,
                            const float* __restrict__ lin_w, const float* __restrict__ lin_b,
                            float* __restrict__ out) {
    // Interleaved (z,h) so the inner loop does one 64-bit broadcast LDS per tap.
    __shared__ float sW[48 * 64 * 2];
    __shared__ float sLin[64];
    __shared__ float sBz[64];
    __shared__ float sBh[64];

    // w_* layout: (2, 2, 80, 64) -> index ((d*2 + k)*80 + c)*64 + f
    const int PLANE = 80 * 64;
    for (int idx = threadIdx.x; idx < 48 * 64; idx += blockDim.x) {
        int ci = idx >> 6;       // 0..47  (effective input channel)
        int f  = idx & 63;       // output filter
        float vz, vh;
        if (ci < 16) {                       // hop 0: W[0,0] + W[1,0], rows :16
            vz = w_z[0 * PLANE + ci * 64 + f] + w_z[2 * PLANE + ci * 64 + f];
            vh = w_h[0 * PLANE + ci * 64 + f] + w_h[2 * PLANE + ci * 64 + f];
        } else if (ci < 32) {                // Tx_o path: W[0,1], rows :16
            int cc = ci - 16;
            vz = w_z[1 * PLANE + cc * 64 + f];
            vh = w_h[1 * PLANE + cc * 64 + f];
        } else {                             // Tx_i path: W[1,1], rows :16
            int cc = ci - 32;
            vz = w_z[3 * PLANE + cc * 64 + f];
            vh = w_h[3 * PLANE + cc * 64 + f];
        }
        sW[idx * 2 + 0] = vz;
        sW[idx * 2 + 1] = vh;
    }
    if (threadIdx.x < 64) {
        sLin[threadIdx.x] = lin_w[threadIdx.x];
        sBz[threadIdx.x]  = b_z[threadIdx.x];
        sBh[threadIdx.x]  = b_h[threadIdx.x];
    }
    __syncthreads();

    int n = blockIdx.x * blockDim.x + threadIdx.x;
    if (n >= N_) return;

    float fv[48];
    const float4* x4 = reinterpret_cast<const float4*>(x);
    const float4* o4 = reinterpret_cast<const float4*>(g_txo);
    const float4* i4 = reinterpret_cast<const float4*>(g_txi);
#pragma unroll
    for (int q = 0; q < 4; q++) {
        float4 v = x4[n * 4 + q];
        fv[q * 4 + 0] = v.x; fv[q * 4 + 1] = v.y; fv[q * 4 + 2] = v.z; fv[q * 4 + 3] = v.w;
        v = o4[n * 4 + q];
        fv[16 + q * 4 + 0] = v.x; fv[16 + q * 4 + 1] = v.y; fv[16 + q * 4 + 2] = v.z; fv[16 + q * 4 + 3] = v.w;
        v = i4[n * 4 + q];
        fv[32 + q * 4 + 0] = v.x; fv[32 + q * 4 + 1] = v.y; fv[32 + q * 4 + 2] = v.z; fv[32 + q * 4 + 3] = v.w;
    }

    const float2* w2 = reinterpret_cast<const float2*>(sW);
    float acc = 0.f;
    for (int j = 0; j < 64; j++) {
        // independent accumulation chains to break FFMA latency serialization
        float az0 = sBz[j], az1 = 0.f;
        float ah0 = sBh[j], ah1 = 0.f;
#pragma unroll
        for (int i = 0; i < 48; i += 2) {
            float2 wa = w2[i * 64 + j];
            float2 wb = w2[(i + 1) * 64 + j];
            az0 += fv[i]     * wa.x;
            ah0 += fv[i]     * wa.y;
            az1 += fv[i + 1] * wb.x;
            ah1 += fv[i + 1] * wb.y;
        }
        float az = az0 + az1;
        float ah = ah0 + ah1;
        float z  = 1.f / (1.f + __expf(-az));
        float ht = tanhf(ah);
        float hv = (1.f - z) * ht;
        hv = fmaxf(hv, 0.f);
        acc += hv * sLin[j];
    }
    out[n] = acc + lin_b[0];
}

extern "C" void kernel_launch(void* const* d_in, const int* in_sizes, int n_in,
                              void* d_out, int out_size) {
    const float* x     = (const float*)d_in[0];
    const int*   ei    = (const int*)d_in[1];   // JAX default: int64 -> int32
    const float* ew    = (const float*)d_in[2];
    const float* w_z   = (const float*)d_in[3];
    const float* b_z   = (const float*)d_in[4];
    // d_in[5] = w_r, d_in[6] = b_r : dead (R gate multiplies H0 == 0)
    const float* w_h   = (const float*)d_in[7];
    const float* b_h   = (const float*)d_in[8];
    const float* lin_w = (const float*)d_in[9];
    const float* lin_b = (const float*)d_in[10];
    float*       out   = (float*)d_out;

    zero_kernel<<<(N_ * 16 + 255) / 256, 256>>>();
    degree_kernel<<<(E_ + 255) / 256, 256>>>(ei, ew);
    scatter_kernel<<<(E_ * 4 + 255) / 256, 256>>>(ei, x);
    node_kernel<<<(N_ + 255) / 256, 256>>>(x, w_z, b_z, w_h, b_h, lin_w, lin_b, out);
}

// round 3
// speedup vs baseline: 1.1447x; 1.1447x over previous
#include <cuda_runtime.h>

constexpr int N_ = 50000;     // nodes
constexpr int E_ = 800000;    // edges
// LAGS=16, FILT=64, CIN=80 — H0==0 kills hidden channels; w_r/b_r dead.

__device__ float  g_deg_out[N_];
__device__ float  g_deg_in[N_];
__device__ __align__(16) float g_txo[N_ * 16];
__device__ __align__(16) float g_txi[N_ * 16];

__global__ void zero_kernel() {
    int i = blockIdx.x * blockDim.x + threadIdx.x;
    if (i < N_ * 16) { g_txo[i] = 0.f; g_txi[i] = 0.f; }
    if (i < N_)      { g_deg_out[i] = 0.f; g_deg_in[i] = 0.f; }
}

__global__ void degree_kernel(const int* __restrict__ ei,
                              const float* __restrict__ ew) {
    int e = blockIdx.x * blockDim.x + threadIdx.x;
    if (e >= E_) return;
    int r = ei[e];
    int c = ei[E_ + e];
    float w = ew[e];
    atomicAdd(&g_deg_out[r], w);
    atomicAdd(&g_deg_in[c], w);
}

__device__ __forceinline__ void red_add_v4(float* p, float a, float b, float c, float d) {
    asm volatile("red.global.add.v4.f32 [%0], {%1,%2,%3,%4};"
                 :: "l"(p), "f"(a), "f"(b), "f"(c), "f"(d) : "memory");
}

// 2 threads per edge: t<E handles out-direction, t>=E handles in-direction.
// Each thread: gather one 64B x-row (L2 hit), scale, 4x RED.128 scatter.
__global__ void scatter_kernel(const int* __restrict__ ei,
                               const float* __restrict__ x) {
    int t = blockIdx.x * blockDim.x + threadIdx.x;
    if (t >= 2 * E_) return;
    const float4* x4 = reinterpret_cast<const float4*>(x);

    if (t < E_) {
        int e = t;
        int r = ei[e];
        int c = ei[E_ + e];
        float d = g_deg_out[r]; d = (d > 0.f) ? d : 1.f;
        float s = 1.f / d;
        float* dst = &g_txo[c * 16];
#pragma unroll
        for (int q = 0; q < 4; q++) {
            float4 v = x4[r * 4 + q];
            red_add_v4(dst + q * 4, s * v.x, s * v.y, s * v.z, s * v.w);
        }
    } else {
        int e = t - E_;
        int r = ei[e];
        int c = ei[E_ + e];
        float d = g_deg_in[c]; d = (d > 0.f) ? d : 1.f;
        float s = 1.f / d;
        float* dst = &g_txi[r * 16];
#pragma unroll
        for (int q = 0; q < 4; q++) {
            float4 v = x4[c * 4 + q];
            red_add_v4(dst + q * 4, s * v.x, s * v.y, s * v.z, s * v.w);
        }
    }
}

__device__ __forceinline__ unsigned long long pack2(float a, float b) {
    unsigned long long v;
    asm("mov.b64 %0, {%1,%2};" : "=l"(v) : "f"(a), "f"(b));
    return v;
}
__device__ __forceinline__ void unpack2(unsigned long long v, float& a, float& b) {
    asm("mov.b64 {%0,%1}, %2;" : "=f"(a), "=f"(b) : "l"(v));
}
__device__ __forceinline__ void fma2(unsigned long long& acc, unsigned long long a, unsigned long long b) {
    asm("fma.rn.f32x2 %0, %1, %2, %0;" : "+l"(acc) : "l"(a), "l"(b));
}

// Per-node fused epilogue, 2 threads per node (each 32 filters, parity-split).
//   F = [x, Tx_o, Tx_i] (48)
//   out = sum_j relu((1-sigmoid(F@Wz_j+bz_j)) * tanh(F@Wh_j+bh_j)) * lin_w_j + lin_b
__global__ void node_kernel(const float* __restrict__ x,
                            const float* __restrict__ w_z, const float* __restrict__ b_z,
                            const float* __restrict__ w_h, const float* __restrict__ b_h,
                            const float* __restrict__ lin_w, const float* __restrict__ lin_b,
                            float* __restrict__ out) {
    __shared__ __align__(16) float sWz[64][48];   // [filter][channel], row = one dot
    __shared__ __align__(16) float sWh[64][48];
    __shared__ float sBz[64];
    __shared__ float sBh[64];
    __shared__ float sLin[64];

    // w_* layout: (2, 2, 80, 64) -> ((d*2 + k)*80 + c)*64 + f
    const int PLANE = 80 * 64;
    for (int idx = threadIdx.x; idx < 48 * 64; idx += blockDim.x) {
        int f  = idx / 48;
        int ci = idx % 48;
        float vz, vh;
        if (ci < 16) {                       // hop 0: W[0,0]+W[1,0], rows :16 (x)
            vz = w_z[0 * PLANE + ci * 64 + f] + w_z[2 * PLANE + ci * 64 + f];
            vh = w_h[0 * PLANE + ci * 64 + f] + w_h[2 * PLANE + ci * 64 + f];
        } else if (ci < 32) {                // Tx_o: W[0,1], rows :16
            int cc = ci - 16;
            vz = w_z[1 * PLANE + cc * 64 + f];
            vh = w_h[1 * PLANE + cc * 64 + f];
        } else {                             // Tx_i: W[1,1], rows :16
            int cc = ci - 32;
            vz = w_z[3 * PLANE + cc * 64 + f];
            vh = w_h[3 * PLANE + cc * 64 + f];
        }
        sWz[f][ci] = vz;
        sWh[f][ci] = vh;
    }
    if (threadIdx.x < 64) {
        sBz[threadIdx.x]  = b_z[threadIdx.x];
        sBh[threadIdx.x]  = b_h[threadIdx.x];
        sLin[threadIdx.x] = lin_w[threadIdx.x];
    }
    __syncthreads();

    int t = blockIdx.x * blockDim.x + threadIdx.x;
    int n = t >> 1;        // node
    int h = t & 1;         // filter parity
    if (n >= N_) return;

    // F vector as 24 packed f32x2 pairs
    unsigned long long fvp[24];
    const float4* x4 = reinterpret_cast<const float4*>(x);
    const float4* o4 = reinterpret_cast<const float4*>(g_txo);
    const float4* i4 = reinterpret_cast<const float4*>(g_txi);
#pragma unroll
    for (int q = 0; q < 4; q++) {
        float4 v = x4[n * 4 + q];
        fvp[q * 2 + 0]      = pack2(v.x, v.y);
        fvp[q * 2 + 1]      = pack2(v.z, v.w);
        v = o4[n * 4 + q];
        fvp[8 + q * 2 + 0]  = pack2(v.x, v.y);
        fvp[8 + q * 2 + 1]  = pack2(v.z, v.w);
        v = i4[n * 4 + q];
        fvp[16 + q * 2 + 0] = pack2(v.x, v.y);
        fvp[16 + q * 2 + 1] = pack2(v.z, v.w);
    }

    const float LOG2E = 1.4426950408889634f;
    float acc = 0.f;
    for (int jj = 0; jj < 32; jj++) {
        int j = 2 * jj + h;   // parity split -> warp's two bcast addrs 16 banks apart
        const unsigned long long* wz = reinterpret_cast<const unsigned long long*>(sWz[j]);
        const unsigned long long* wh = reinterpret_cast<const unsigned long long*>(sWh[j]);
        unsigned long long az2 = 0ull, ah2 = 0ull;
#pragma unroll
        for (int i = 0; i < 24; i++) {
            fma2(az2, wz[i], fvp[i]);
            fma2(ah2, wh[i], fvp[i]);
        }
        float a0, a1, az, ah;
        unpack2(az2, a0, a1); az = a0 + a1 + sBz[j];
        unpack2(ah2, a0, a1); ah = a0 + a1 + sBh[j];

        // (1 - sigmoid(az)) = 1/(1 + e^{az})
        float t0;
        asm("ex2.approx.f32 %0, %1;" : "=f"(t0) : "f"(az * LOG2E));
        float s;
        asm("rcp.approx.f32 %0, %1;" : "=f"(s) : "f"(1.f + t0));
        float ht;
        asm("tanh.approx.f32 %0, %1;" : "=f"(ht) : "f"(ah));
        float hv = fmaxf(s * ht, 0.f);
        acc = fmaf(hv, sLin[j], acc);
    }

    // combine the two filter-halves of this node
    acc += __shfl_xor_sync(0xffffffffu, acc, 1);
    if (h == 0) out[n] = acc + lin_b[0];
}

extern "C" void kernel_launch(void* const* d_in, const int* in_sizes, int n_in,
                              void* d_out, int out_size) {
    const float* x     = (const float*)d_in[0];
    const int*   ei    = (const int*)d_in[1];   // jnp.int64 materializes as int32 (x64 off)
    const float* ew    = (const float*)d_in[2];
    const float* w_z   = (const float*)d_in[3];
    const float* b_z   = (const float*)d_in[4];
    // d_in[5] = w_r, d_in[6] = b_r : dead (R gate multiplies H0 == 0)
    const float* w_h   = (const float*)d_in[7];
    const float* b_h   = (const float*)d_in[8];
    const float* lin_w = (const float*)d_in[9];
    const float* lin_b = (const float*)d_in[10];
    float*       out   = (float*)d_out;

    zero_kernel<<<(N_ * 16 + 255) / 256, 256>>>();
    degree_kernel<<<(E_ + 255) / 256, 256>>>(ei, ew);
    scatter_kernel<<<(2 * E_ + 255) / 256, 256>>>(ei, x);
    node_kernel<<<(2 * N_ + 255) / 256, 256>>>(x, w_z, b_z, w_h, b_h, lin_w, lin_b, out);
}